// round 11
// baseline (speedup 1.0000x reference)
#include <cuda_runtime.h>
#include <cuda_fp16.h>
#include <cstdint>

// CoherenceGate via fp16 mma.sync.m16n8k16 (sm_100 baseline ISA).
// out = sigmoid( psi_re*(psi_re@W^T) + psi_im*(psi_im@W^T) + bias )
// B=8192, K=1024.
//
// R11: R10 + warp-skewed k-chunk order inside each slice (wid&3 rotation) to
//      de-phase the ldsm/mma convoys: smem crossbar and tensor pipe overlap
//      instead of alternating. Everything else identical to R10 (118.8us).

#define KDIM 1024
#define BDIM 8192
#define BM 64
#define BN 128
#define BK 64
#define NTHREADS 256
#define PIPE 3
#define NS (KDIM / BK)      // 16
#define NTILES ((BDIM / BM) * (KDIM / BN))   // 1024
#define GRID_PERSIST 296

#define W_SCALE 256.0f
#define W_INV   (1.0f / 256.0f)

#define OFF_ARE 0
#define OFF_AIM 8192
#define OFF_W   16384
#define STAGE_BYTES 32768
#define SMEM_BYTES (PIPE * STAGE_BYTES)   // 98304 per CTA

#define CVT_BLKS_RE 576
#define CVT_BLKS_IM 576
#define CVT_BLKS_W  128
#define CVT_BLKS (CVT_BLKS_RE + CVT_BLKS_IM + CVT_BLKS_W)   // 1280

__device__ __half g_pre16[(size_t)BDIM * KDIM];
__device__ __half g_pim16[(size_t)BDIM * KDIM];
__device__ __half g_W16[(size_t)KDIM * KDIM];
__device__ unsigned g_tile_ctr;

__device__ __forceinline__ uint32_t smem_u32(const void* p) {
    uint32_t a;
    asm("{ .reg .u64 t; cvta.to.shared.u64 t, %1; cvt.u32.u64 %0, t; }" : "=r"(a) : "l"(p));
    return a;
}
__device__ __forceinline__ void cp16(uint32_t dst, const void* src) {
    asm volatile("cp.async.cg.shared.global [%0], [%1], 16;" :: "r"(dst), "l"(src) : "memory");
}
__device__ __forceinline__ void ldsm4(uint32_t* r, uint32_t addr) {
    asm volatile("ldmatrix.sync.aligned.m8n8.x4.shared.b16 {%0,%1,%2,%3}, [%4];"
                 : "=r"(r[0]), "=r"(r[1]), "=r"(r[2]), "=r"(r[3]) : "r"(addr));
}
__device__ __forceinline__ void mma16(float* d, const uint32_t* a, const uint32_t* b) {
    asm volatile(
        "mma.sync.aligned.m16n8k16.row.col.f32.f16.f16.f32 "
        "{%0,%1,%2,%3},{%4,%5,%6,%7},{%8,%9},{%0,%1,%2,%3};"
        : "+f"(d[0]), "+f"(d[1]), "+f"(d[2]), "+f"(d[3])
        : "r"(a[0]), "r"(a[1]), "r"(a[2]), "r"(a[3]), "r"(b[0]), "r"(b[1]));
}
__device__ __forceinline__ float sigf(float x) {
    float t;
    asm("tanh.approx.f32 %0, %1;" : "=f"(t) : "f"(0.5f * x));
    return fmaf(0.5f, t, 0.5f);
}

// ---------------- phase 1: single partitioned convert kernel ----------------
__device__ __forceinline__ void cvt_range(const float4* __restrict__ src, uint2* __restrict__ dst,
                                          int n4, int nblk, int blk, float scale)
{
    const int stride = nblk * 256;
    for (int i = blk * 256 + threadIdx.x; i < n4; i += stride) {
        const float4 v = src[i];
        const __half2 h0 = __floats2half2_rn(v.x * scale, v.y * scale);
        const __half2 h1 = __floats2half2_rn(v.z * scale, v.w * scale);
        uint2 o;
        o.x = *(const uint32_t*)&h0;
        o.y = *(const uint32_t*)&h1;
        dst[i] = o;
    }
}

__global__ void cvt_all_kernel(const float4* __restrict__ pre,
                               const float4* __restrict__ pim,
                               const float4* __restrict__ Wm)
{
    if (blockIdx.x == 0 && threadIdx.x == 0) g_tile_ctr = 0u;

    const int N_PSI4 = (BDIM * KDIM) / 4;
    const int N_W4   = (KDIM * KDIM) / 4;
    const int b = blockIdx.x;

    if (b < CVT_BLKS_RE) {
        cvt_range(pre, (uint2*)g_pre16, N_PSI4, CVT_BLKS_RE, b, 1.0f);
    } else if (b < CVT_BLKS_RE + CVT_BLKS_IM) {
        cvt_range(pim, (uint2*)g_pim16, N_PSI4, CVT_BLKS_IM, b - CVT_BLKS_RE, 1.0f);
    } else {
        cvt_range(Wm, (uint2*)g_W16, N_W4, CVT_BLKS_W, b - CVT_BLKS_RE - CVT_BLKS_IM, W_SCALE);
    }
}

// ---------------- stage loader (8 cp.async / thread) ----------------
__device__ __forceinline__ void load_stage(uint32_t sbase, int buf, int j0,
                                           int block_b, int block_k, int tid)
{
    const uint32_t sb = sbase + (uint32_t)buf * STAGE_BYTES;
#pragma unroll
    for (int t = 0; t < 2; ++t) {
        const int idx = tid + t * 256;
        const int row = idx >> 3;
        const int ch  = idx & 7;
        const uint32_t so = (uint32_t)(row * 128 + ((ch ^ (row & 7)) * 16));
        const size_t ga = (size_t)(block_b + row) * KDIM + j0 + ch * 8;
        cp16(sb + OFF_ARE + so, g_pre16 + ga);
        cp16(sb + OFF_AIM + so, g_pim16 + ga);
    }
#pragma unroll
    for (int t = 0; t < 4; ++t) {
        const int idx = tid + t * 256;
        const int row = idx >> 3;
        const int ch  = idx & 7;
        const uint32_t so = (uint32_t)(row * 128 + ((ch ^ (row & 7)) * 16));
        cp16(sb + OFF_W + so, g_W16 + (size_t)(block_k + row) * KDIM + j0 + ch * 8);
    }
}

__device__ __forceinline__ void prologue_tile(uint32_t sbase, int block_b, int block_k, int tid)
{
    load_stage(sbase, 0, 0, block_b, block_k, tid);
    asm volatile("cp.async.commit_group;" ::: "memory");
    load_stage(sbase, 1, BK, block_b, block_k, tid);
    asm volatile("cp.async.commit_group;" ::: "memory");
}

// ---------------- phase 2: persistent dual-GEMM + fused sigmoid ----------------
__global__ __launch_bounds__(NTHREADS, 2)
void coherence_gate_h(const float* __restrict__ pre,
                      const float* __restrict__ pim,
                      const float* __restrict__ bias,
                      float* __restrict__ out)
{
    extern __shared__ __align__(128) char smem[];
    const uint32_t sbase = smem_u32(smem);
    __shared__ unsigned s_next;

    const int tid    = threadIdx.x;
    const int wid    = tid >> 5;
    const int lane   = tid & 31;
    const int g      = lane >> 2;
    const int tg     = lane & 3;
    const int warp_m = wid >> 2;   // 0..1 -> 32-row band
    const int warp_n = wid & 3;    // 0..3 -> 32-col band
    const int kskew  = wid & 3;    // per-warp k-chunk rotation
    const bool wfirst = (wid & 1); // alternate ldsm issue order by parity

    const int a_rl  = lane & 15;
    const int a_chi = lane >> 4;
    const int w_M   = lane >> 3;
    const int w_r   = lane & 7;
    const int w_kc  = w_M & 1;
    const int w_nadd = (w_M >> 1) * 8;

    int abase[2], axor[2];
#pragma unroll
    for (int mt = 0; mt < 2; ++mt) {
        const int arow = warp_m * 32 + mt * 16 + a_rl;
        abase[mt] = arow * 128;
        axor[mt]  = arow & 7;
    }
    int wbase[2], wxor[2];
#pragma unroll
    for (int ntp = 0; ntp < 2; ++ntp) {
        const int wrow = warp_n * 32 + ntp * 16 + w_nadd + w_r;
        wbase[ntp] = wrow * 128;
        wxor[ntp]  = wrow & 7;
    }

    if (tid == 0) s_next = atomicAdd(&g_tile_ctr, 1u);
    __syncthreads();
    unsigned t = s_next;
    if (t >= NTILES) return;
    {
        const int bb = (int)(t >> 3) * BM;
        const int bk = (int)(t & 7) * BN;
        prologue_tile(sbase, bb, bk, tid);
    }

    for (;;) {
        const int block_b = (int)(t >> 3) * BM;
        const int block_k = (int)(t & 7) * BN;

        __syncthreads();
        if (tid == 0) s_next = atomicAdd(&g_tile_ctr, 1u);

        float dre[2][4][4], dim_[2][4][4];
#pragma unroll
        for (int mt = 0; mt < 2; ++mt)
#pragma unroll
            for (int nt = 0; nt < 4; ++nt)
#pragma unroll
                for (int q = 0; q < 4; ++q) { dre[mt][nt][q] = 0.f; dim_[mt][nt][q] = 0.f; }

        // -------- mainloop: 16 BK=64 slices --------
        for (int s = 0; s < NS; ++s) {
            asm volatile("cp.async.wait_group 1;" ::: "memory");
            __syncthreads();

            const int ls = s + PIPE - 1;
            if (ls < NS)
                load_stage(sbase, ls % PIPE, ls * BK, block_b, block_k, tid);
            asm volatile("cp.async.commit_group;" ::: "memory");

            const uint32_t sb = sbase + (uint32_t)(s % PIPE) * STAGE_BYTES;

#pragma unroll
            for (int ksi = 0; ksi < 4; ++ksi) {
                const int ks = (ksi + kskew) & 3;   // warp-skewed k-chunk order
                uint32_t ar[2][4], ai[2][4], bw[2][4];
                if (wfirst) {
#pragma unroll
                    for (int ntp = 0; ntp < 2; ++ntp) {
                        const uint32_t wo = (uint32_t)(wbase[ntp] +
                                            (((2 * ks + w_kc) ^ wxor[ntp]) * 16));
                        ldsm4(bw[ntp], sb + OFF_W + wo);
                    }
#pragma unroll
                    for (int mt = 0; mt < 2; ++mt) {
                        const uint32_t ao = (uint32_t)(abase[mt] +
                                            (((2 * ks + a_chi) ^ axor[mt]) * 16));
                        ldsm4(ar[mt], sb + OFF_ARE + ao);
                        ldsm4(ai[mt], sb + OFF_AIM + ao);
                    }
                } else {
#pragma unroll
                    for (int mt = 0; mt < 2; ++mt) {
                        const uint32_t ao = (uint32_t)(abase[mt] +
                                            (((2 * ks + a_chi) ^ axor[mt]) * 16));
                        ldsm4(ar[mt], sb + OFF_ARE + ao);
                        ldsm4(ai[mt], sb + OFF_AIM + ao);
                    }
#pragma unroll
                    for (int ntp = 0; ntp < 2; ++ntp) {
                        const uint32_t wo = (uint32_t)(wbase[ntp] +
                                            (((2 * ks + w_kc) ^ wxor[ntp]) * 16));
                        ldsm4(bw[ntp], sb + OFF_W + wo);
                    }
                }
#pragma unroll
                for (int mt = 0; mt < 2; ++mt)
#pragma unroll
                    for (int nt = 0; nt < 4; ++nt) {
                        mma16(dre[mt][nt],  ar[mt], &bw[nt >> 1][(nt & 1) * 2]);
                        mma16(dim_[mt][nt], ai[mt], &bw[nt >> 1][(nt & 1) * 2]);
                    }
            }
        }

        __syncthreads();
        const unsigned tn = s_next;

        if (tn < NTILES) {
            const int bb = (int)(tn >> 3) * BM;
            const int bk = (int)(tn & 7) * BN;
            prologue_tile(sbase, bb, bk, tid);
        }

        // -------- epilogue (fp32 psi reads; undo W_SCALE; tanh sigmoid) --------
#pragma unroll
        for (int mt = 0; mt < 2; ++mt) {
#pragma unroll
            for (int rr = 0; rr < 2; ++rr) {
                const int row = block_b + warp_m * 32 + mt * 16 + g + rr * 8;
                const size_t brow = (size_t)row * KDIM;
#pragma unroll
                for (int nt = 0; nt < 4; ++nt) {
                    const int k = block_k + warp_n * 32 + nt * 8 + 2 * tg;
                    const float2 xr = *(const float2*)&pre[brow + k];
                    const float2 xi = *(const float2*)&pim[brow + k];
                    const float2 bv = *(const float2*)&bias[k];
                    const float ur0 = dre[mt][nt][rr * 2 + 0] * W_INV;
                    const float ur1 = dre[mt][nt][rr * 2 + 1] * W_INV;
                    const float ui0 = dim_[mt][nt][rr * 2 + 0] * W_INV;
                    const float ui1 = dim_[mt][nt][rr * 2 + 1] * W_INV;
                    float2 o;
                    o.x = sigf(fmaf(xr.x, ur0, fmaf(xi.x, ui0, bv.x)));
                    o.y = sigf(fmaf(xr.y, ur1, fmaf(xi.y, ui1, bv.y)));
                    *(float2*)&out[brow + k] = o;
                }
            }
        }

        if (tn >= NTILES) break;
        t = tn;
    }
}

extern "C" void kernel_launch(void* const* d_in, const int* in_sizes, int n_in,
                              void* d_out, int out_size)
{
    const float* pre  = (const float*)d_in[0];
    const float* pim  = (const float*)d_in[1];
    const float* Wm   = (const float*)d_in[2];
    const float* bias = (const float*)d_in[3];
    float* out = (float*)d_out;

    cvt_all_kernel<<<CVT_BLKS, 256>>>((const float4*)pre, (const float4*)pim,
                                      (const float4*)Wm);

    cudaFuncSetAttribute(coherence_gate_h,
                         cudaFuncAttributeMaxDynamicSharedMemorySize, SMEM_BYTES);
    coherence_gate_h<<<GRID_PERSIST, NTHREADS, SMEM_BYTES>>>(pre, pim, bias, out);
}

// round 12
// speedup vs baseline: 1.0356x; 1.0356x over previous
#include <cuda_runtime.h>
#include <cuda_fp16.h>
#include <cstdint>

// CoherenceGate via fp16 mma.sync.m16n8k16 (sm_100 baseline ISA).
// out = sigmoid( psi_re*(psi_re@W^T) + psi_im*(psi_im@W^T) + bias )
// B=8192, K=1024.
//
// R12: exact R10 GEMM (best measured: 118.8us total) + convert kernel
//      repartitioned to a single co-resident wave (1136 blocks <= ~1184
//      capacity at 8 blocks/SM) to remove its wave tail.

#define KDIM 1024
#define BDIM 8192
#define BM 64
#define BN 128
#define BK 64
#define NTHREADS 256
#define PIPE 3
#define NS (KDIM / BK)      // 16
#define NTILES ((BDIM / BM) * (KDIM / BN))   // 1024
#define GRID_PERSIST 296

#define W_SCALE 256.0f
#define W_INV   (1.0f / 256.0f)

#define OFF_ARE 0
#define OFF_AIM 8192
#define OFF_W   16384
#define STAGE_BYTES 32768
#define SMEM_BYTES (PIPE * STAGE_BYTES)   // 98304 per CTA

// convert kernel partition: single wave (<= ~1184 co-resident blocks)
#define CVT_BLKS_RE 528
#define CVT_BLKS_IM 528
#define CVT_BLKS_W  80
#define CVT_BLKS (CVT_BLKS_RE + CVT_BLKS_IM + CVT_BLKS_W)   // 1136

__device__ __half g_pre16[(size_t)BDIM * KDIM];
__device__ __half g_pim16[(size_t)BDIM * KDIM];
__device__ __half g_W16[(size_t)KDIM * KDIM];
__device__ unsigned g_tile_ctr;

__device__ __forceinline__ uint32_t smem_u32(const void* p) {
    uint32_t a;
    asm("{ .reg .u64 t; cvta.to.shared.u64 t, %1; cvt.u32.u64 %0, t; }" : "=r"(a) : "l"(p));
    return a;
}
__device__ __forceinline__ void cp16(uint32_t dst, const void* src) {
    asm volatile("cp.async.cg.shared.global [%0], [%1], 16;" :: "r"(dst), "l"(src) : "memory");
}
__device__ __forceinline__ void ldsm4(uint32_t* r, uint32_t addr) {
    asm volatile("ldmatrix.sync.aligned.m8n8.x4.shared.b16 {%0,%1,%2,%3}, [%4];"
                 : "=r"(r[0]), "=r"(r[1]), "=r"(r[2]), "=r"(r[3]) : "r"(addr));
}
__device__ __forceinline__ void mma16(float* d, const uint32_t* a, const uint32_t* b) {
    asm volatile(
        "mma.sync.aligned.m16n8k16.row.col.f32.f16.f16.f32 "
        "{%0,%1,%2,%3},{%4,%5,%6,%7},{%8,%9},{%0,%1,%2,%3};"
        : "+f"(d[0]), "+f"(d[1]), "+f"(d[2]), "+f"(d[3])
        : "r"(a[0]), "r"(a[1]), "r"(a[2]), "r"(a[3]), "r"(b[0]), "r"(b[1]));
}
__device__ __forceinline__ float sigf(float x) {
    float t;
    asm("tanh.approx.f32 %0, %1;" : "=f"(t) : "f"(0.5f * x));
    return fmaf(0.5f, t, 0.5f);
}

// ---------------- phase 1: single partitioned convert kernel ----------------
__device__ __forceinline__ void cvt_range(const float4* __restrict__ src, uint2* __restrict__ dst,
                                          int n4, int nblk, int blk, float scale)
{
    const int stride = nblk * 256;
    for (int i = blk * 256 + threadIdx.x; i < n4; i += stride) {
        const float4 v = src[i];
        const __half2 h0 = __floats2half2_rn(v.x * scale, v.y * scale);
        const __half2 h1 = __floats2half2_rn(v.z * scale, v.w * scale);
        uint2 o;
        o.x = *(const uint32_t*)&h0;
        o.y = *(const uint32_t*)&h1;
        dst[i] = o;
    }
}

__global__ void cvt_all_kernel(const float4* __restrict__ pre,
                               const float4* __restrict__ pim,
                               const float4* __restrict__ Wm)
{
    if (blockIdx.x == 0 && threadIdx.x == 0) g_tile_ctr = 0u;

    const int N_PSI4 = (BDIM * KDIM) / 4;
    const int N_W4   = (KDIM * KDIM) / 4;
    const int b = blockIdx.x;

    if (b < CVT_BLKS_RE) {
        cvt_range(pre, (uint2*)g_pre16, N_PSI4, CVT_BLKS_RE, b, 1.0f);
    } else if (b < CVT_BLKS_RE + CVT_BLKS_IM) {
        cvt_range(pim, (uint2*)g_pim16, N_PSI4, CVT_BLKS_IM, b - CVT_BLKS_RE, 1.0f);
    } else {
        cvt_range(Wm, (uint2*)g_W16, N_W4, CVT_BLKS_W, b - CVT_BLKS_RE - CVT_BLKS_IM, W_SCALE);
    }
}

// ---------------- stage loader (8 cp.async / thread) ----------------
__device__ __forceinline__ void load_stage(uint32_t sbase, int buf, int j0,
                                           int block_b, int block_k, int tid)
{
    const uint32_t sb = sbase + (uint32_t)buf * STAGE_BYTES;
#pragma unroll
    for (int t = 0; t < 2; ++t) {
        const int idx = tid + t * 256;
        const int row = idx >> 3;
        const int ch  = idx & 7;
        const uint32_t so = (uint32_t)(row * 128 + ((ch ^ (row & 7)) * 16));
        const size_t ga = (size_t)(block_b + row) * KDIM + j0 + ch * 8;
        cp16(sb + OFF_ARE + so, g_pre16 + ga);
        cp16(sb + OFF_AIM + so, g_pim16 + ga);
    }
#pragma unroll
    for (int t = 0; t < 4; ++t) {
        const int idx = tid + t * 256;
        const int row = idx >> 3;
        const int ch  = idx & 7;
        const uint32_t so = (uint32_t)(row * 128 + ((ch ^ (row & 7)) * 16));
        cp16(sb + OFF_W + so, g_W16 + (size_t)(block_k + row) * KDIM + j0 + ch * 8);
    }
}

__device__ __forceinline__ void prologue_tile(uint32_t sbase, int block_b, int block_k, int tid)
{
    load_stage(sbase, 0, 0, block_b, block_k, tid);
    asm volatile("cp.async.commit_group;" ::: "memory");
    load_stage(sbase, 1, BK, block_b, block_k, tid);
    asm volatile("cp.async.commit_group;" ::: "memory");
}

// ---------------- phase 2: persistent dual-GEMM + fused sigmoid ----------------
__global__ __launch_bounds__(NTHREADS, 2)
void coherence_gate_h(const float* __restrict__ pre,
                      const float* __restrict__ pim,
                      const float* __restrict__ bias,
                      float* __restrict__ out)
{
    extern __shared__ __align__(128) char smem[];
    const uint32_t sbase = smem_u32(smem);
    __shared__ unsigned s_next;

    const int tid    = threadIdx.x;
    const int wid    = tid >> 5;
    const int lane   = tid & 31;
    const int g      = lane >> 2;
    const int tg     = lane & 3;
    const int warp_m = wid >> 2;   // 0..1 -> 32-row band
    const int warp_n = wid & 3;    // 0..3 -> 32-col band

    const int a_rl  = lane & 15;
    const int a_chi = lane >> 4;
    const int w_M   = lane >> 3;
    const int w_r   = lane & 7;
    const int w_kc  = w_M & 1;
    const int w_nadd = (w_M >> 1) * 8;

    int abase[2], axor[2];
#pragma unroll
    for (int mt = 0; mt < 2; ++mt) {
        const int arow = warp_m * 32 + mt * 16 + a_rl;
        abase[mt] = arow * 128;
        axor[mt]  = arow & 7;
    }
    int wbase[2], wxor[2];
#pragma unroll
    for (int ntp = 0; ntp < 2; ++ntp) {
        const int wrow = warp_n * 32 + ntp * 16 + w_nadd + w_r;
        wbase[ntp] = wrow * 128;
        wxor[ntp]  = wrow & 7;
    }

    if (tid == 0) s_next = atomicAdd(&g_tile_ctr, 1u);
    __syncthreads();
    unsigned t = s_next;
    if (t >= NTILES) return;
    {
        const int bb = (int)(t >> 3) * BM;
        const int bk = (int)(t & 7) * BN;
        prologue_tile(sbase, bb, bk, tid);
    }

    for (;;) {
        const int block_b = (int)(t >> 3) * BM;
        const int block_k = (int)(t & 7) * BN;

        __syncthreads();
        if (tid == 0) s_next = atomicAdd(&g_tile_ctr, 1u);

        float dre[2][4][4], dim_[2][4][4];
#pragma unroll
        for (int mt = 0; mt < 2; ++mt)
#pragma unroll
            for (int nt = 0; nt < 4; ++nt)
#pragma unroll
                for (int q = 0; q < 4; ++q) { dre[mt][nt][q] = 0.f; dim_[mt][nt][q] = 0.f; }

        // -------- mainloop: 16 BK=64 slices (R10-proven structure) --------
        for (int s = 0; s < NS; ++s) {
            asm volatile("cp.async.wait_group 1;" ::: "memory");
            __syncthreads();

            const int ls = s + PIPE - 1;
            if (ls < NS)
                load_stage(sbase, ls % PIPE, ls * BK, block_b, block_k, tid);
            asm volatile("cp.async.commit_group;" ::: "memory");

            const uint32_t sb = sbase + (uint32_t)(s % PIPE) * STAGE_BYTES;

#pragma unroll
            for (int ks = 0; ks < 4; ++ks) {
                uint32_t ar[2][4], ai[2][4], bw[2][4];
#pragma unroll
                for (int mt = 0; mt < 2; ++mt) {
                    const uint32_t ao = (uint32_t)(abase[mt] +
                                        (((2 * ks + a_chi) ^ axor[mt]) * 16));
                    ldsm4(ar[mt], sb + OFF_ARE + ao);
                    ldsm4(ai[mt], sb + OFF_AIM + ao);
                }
#pragma unroll
                for (int ntp = 0; ntp < 2; ++ntp) {
                    const uint32_t wo = (uint32_t)(wbase[ntp] +
                                        (((2 * ks + w_kc) ^ wxor[ntp]) * 16));
                    ldsm4(bw[ntp], sb + OFF_W + wo);
                }
#pragma unroll
                for (int mt = 0; mt < 2; ++mt)
#pragma unroll
                    for (int nt = 0; nt < 4; ++nt) {
                        mma16(dre[mt][nt],  ar[mt], &bw[nt >> 1][(nt & 1) * 2]);
                        mma16(dim_[mt][nt], ai[mt], &bw[nt >> 1][(nt & 1) * 2]);
                    }
            }
        }

        __syncthreads();
        const unsigned tn = s_next;

        // next tile's prologue overlaps this tile's epilogue
        if (tn < NTILES) {
            const int bb = (int)(tn >> 3) * BM;
            const int bk = (int)(tn & 7) * BN;
            prologue_tile(sbase, bb, bk, tid);
        }

        // -------- epilogue (fp32 psi reads; undo W_SCALE; tanh sigmoid) --------
#pragma unroll
        for (int mt = 0; mt < 2; ++mt) {
#pragma unroll
            for (int rr = 0; rr < 2; ++rr) {
                const int row = block_b + warp_m * 32 + mt * 16 + g + rr * 8;
                const size_t brow = (size_t)row * KDIM;
#pragma unroll
                for (int nt = 0; nt < 4; ++nt) {
                    const int k = block_k + warp_n * 32 + nt * 8 + 2 * tg;
                    const float2 xr = *(const float2*)&pre[brow + k];
                    const float2 xi = *(const float2*)&pim[brow + k];
                    const float2 bv = *(const float2*)&bias[k];
                    const float ur0 = dre[mt][nt][rr * 2 + 0] * W_INV;
                    const float ur1 = dre[mt][nt][rr * 2 + 1] * W_INV;
                    const float ui0 = dim_[mt][nt][rr * 2 + 0] * W_INV;
                    const float ui1 = dim_[mt][nt][rr * 2 + 1] * W_INV;
                    float2 o;
                    o.x = sigf(fmaf(xr.x, ur0, fmaf(xi.x, ui0, bv.x)));
                    o.y = sigf(fmaf(xr.y, ur1, fmaf(xi.y, ui1, bv.y)));
                    *(float2*)&out[brow + k] = o;
                }
            }
        }

        if (tn >= NTILES) break;
        t = tn;
    }
}

extern "C" void kernel_launch(void* const* d_in, const int* in_sizes, int n_in,
                              void* d_out, int out_size)
{
    const float* pre  = (const float*)d_in[0];
    const float* pim  = (const float*)d_in[1];
    const float* Wm   = (const float*)d_in[2];
    const float* bias = (const float*)d_in[3];
    float* out = (float*)d_out;

    cvt_all_kernel<<<CVT_BLKS, 256>>>((const float4*)pre, (const float4*)pim,
                                      (const float4*)Wm);

    cudaFuncSetAttribute(coherence_gate_h,
                         cudaFuncAttributeMaxDynamicSharedMemorySize, SMEM_BYTES);
    coherence_gate_h<<<GRID_PERSIST, NTHREADS, SMEM_BYTES>>>(pre, pim, bias, out);
}